// round 2
// baseline (speedup 1.0000x reference)
#include <cuda_runtime.h>
#include <math.h>

#define Nn 10000
#define Ne 160000

// ---------------- scratch (device globals; no allocation allowed) ----------
__device__ float g_s_up [Nn*64];
__device__ float g_v_up [Nn*192];        // [n][c*3+i]
__device__ float g_skip_s[Nn*128];
__device__ float g_skip_v[Nn*192];       // [n][c*3+i]
__device__ float g_agg_s[Nn*128];
__device__ float g_agg_v[Nn*576];        // [n][i][o] : i<3, o<192
__device__ float g_mix  [(size_t)Ne*320];

__device__ __forceinline__ float sw(float x){ return x/(1.f+__expf(-x)); }

__device__ __forceinline__ void red4(float* p, float a, float b, float c, float d){
    asm volatile("red.global.add.v4.f32 [%0], {%1,%2,%3,%4};"
                 :: "l"(p), "f"(a), "f"(b), "f"(c), "f"(d) : "memory");
}

// ---------------- K1: node prep (s_up, v_up, skip_s, skip_v) ---------------
__global__ __launch_bounds__(256) void k_node_prep(
    const float* __restrict__ ns, const float* __restrict__ nv,
    const int*   __restrict__ spec,
    const float* __restrict__ Wss, const float* __restrict__ Wsv,
    const float* __restrict__ Wus, const float* __restrict__ Wuv)
{
    __shared__ float sWus[4096], sWuv[4096];
    __shared__ float stage[8][256];
    int tid = threadIdx.x;
    for(int i=tid;i<4096;i+=256){ sWus[i]=Wus[i]; sWuv[i]=Wuv[i]; }
    __syncthreads();
    int warp = tid>>5, lane = tid&31;
    int gw = blockIdx.x*8+warp, nw = gridDim.x*8;
    for(int n=gw; n<Nn; n+=nw){
        float* st = stage[warp];
        for(int i=lane;i<64;i+=32)  st[i]    = ns[n*64+i];
        for(int i=lane;i<192;i+=32) st[64+i] = nv[n*192+i];
        __syncwarp();
        int sp = spec[n];
        const float* wss = Wss + sp*8192;   // [64][128]
        const float* wsv = Wsv + sp*4096;   // [64][64]
        float asu0=0.f, asu1=0.f;
        float avu[2][3]={{0,0,0},{0,0,0}};
        float aks[4]={0,0,0,0};
        float akv[2][3]={{0,0,0},{0,0,0}};
        for(int c=0;c<64;c++){
            float s  = st[c];
            float v0 = st[64+3*c], v1 = st[64+3*c+1], v2 = st[64+3*c+2];
            float w0 = sWus[c*64+lane], w1 = sWus[c*64+lane+32];
            asu0 += s*w0; asu1 += s*w1;
            float u0 = sWuv[c*64+lane], u1 = sWuv[c*64+lane+32];
            avu[0][0]+=v0*u0; avu[0][1]+=v1*u0; avu[0][2]+=v2*u0;
            avu[1][0]+=v0*u1; avu[1][1]+=v1*u1; avu[1][2]+=v2*u1;
            #pragma unroll
            for(int j=0;j<4;j++) aks[j] += s*wss[c*128+lane+32*j];
            float k0 = wsv[c*64+lane], k1 = wsv[c*64+lane+32];
            akv[0][0]+=v0*k0; akv[0][1]+=v1*k0; akv[0][2]+=v2*k0;
            akv[1][0]+=v0*k1; akv[1][1]+=v1*k1; akv[1][2]+=v2*k1;
        }
        const float sc = 0.125f;   // 1/sqrt(64)
        g_s_up[n*64+lane]    = asu0*sc;
        g_s_up[n*64+lane+32] = asu1*sc;
        #pragma unroll
        for(int i=0;i<3;i++){
            g_v_up[n*192+3*lane+i]      = avu[0][i]*sc;
            g_v_up[n*192+3*(lane+32)+i] = avu[1][i]*sc;
        }
        #pragma unroll
        for(int j=0;j<4;j++) g_skip_s[n*128+lane+32*j] = aks[j]*sc;
        #pragma unroll
        for(int j=0;j<2;j++)
            #pragma unroll
            for(int i=0;i<3;i++)
                g_skip_v[n*192+3*(lane+32*j)+i] = akv[j][i]*sc;
        __syncwarp();
    }
}

// ---------------- K2: fused radial MLP -> mix [E,320] ----------------------
// smem floats: W1 512 | W2 4096 | W3 20480 | rad 512 | h1 64*65 | h2 64*65
#define MLP_SMEM_FLOATS (512+4096+20480+512+4160+4160)
__global__ __launch_bounds__(256) void k_mlp(
    const float* __restrict__ vecs,
    const float* __restrict__ W1, const float* __restrict__ W2,
    const float* __restrict__ W3)
{
    extern __shared__ float sm[];
    float* sW1 = sm;
    float* sW2 = sW1+512;
    float* sW3 = sW2+4096;
    float* sRad= sW3+20480;
    float* sH1 = sRad+512;
    float* sH2 = sH1+4160;
    int tid = threadIdx.x;
    for(int i=tid;i<512;i+=256)   sW1[i]=W1[i];
    for(int i=tid;i<4096;i+=256)  sW2[i]=W2[i];
    for(int i=tid;i<20480;i+=256) sW3[i]=W3[i];
    __syncthreads();

    const float PI = 3.14159265358979f;
    const float SQRT2 = 1.41421356237f;

    for(int tile=blockIdx.x; tile<Ne/64; tile+=gridDim.x){
        int ebase = tile*64;
        // ---- radial embedding
        if(tid < 64){
            int e = ebase + tid;
            float x = vecs[3*e], y = vecs[3*e+1], z = vecs[3*e+2];
            float r = sqrtf(x*x+y*y+z*z);
            float r2 = r*r, r3 = r2*r;
            float x6 = r3*r3;
            float env = 1.f - 28.f*x6 + 48.f*x6*r - 21.f*x6*r2;
            if(r >= 1.f) env = 0.f;
            float coef = SQRT2*env/r;
            float pr = PI*r;
            #pragma unroll
            for(int k=0;k<8;k++) sRad[tid*8+k] = coef*sinf((float)(k+1)*pr);
        }
        __syncthreads();
        // ---- h1 = swish(rad @ W1 / sqrt(8))     (64x64)
        {
            int e = tid>>2, o0 = tid&3;
            float acc[16];
            #pragma unroll
            for(int j=0;j<16;j++) acc[j]=0.f;
            #pragma unroll
            for(int k=0;k<8;k++){
                float r = sRad[e*8+k];
                #pragma unroll
                for(int j=0;j<16;j++) acc[j] += r*sW1[k*64+o0+4*j];
            }
            #pragma unroll
            for(int j=0;j<16;j++) sH1[e*65+o0+4*j] = sw(acc[j]*0.35355339059f);
        }
        __syncthreads();
        // ---- h2 = swish(h1 @ W2 / 8)            (64x64)
        {
            int e = tid>>2, o0 = tid&3;
            float acc[16];
            #pragma unroll
            for(int j=0;j<16;j++) acc[j]=0.f;
            for(int k=0;k<64;k++){
                float h = sH1[e*65+k];
                #pragma unroll
                for(int j=0;j<16;j++) acc[j] += h*sW2[k*64+o0+4*j];
            }
            #pragma unroll
            for(int j=0;j<16;j++) sH2[e*65+o0+4*j] = sw(acc[j]*0.125f);
        }
        __syncthreads();
        // ---- mix = h2 @ W3 / 8  (fold scatter inv 0.25)  (64x320)
        {
            int eg = tid>>4, oo = tid&15;
            float acc[4][20];
            #pragma unroll
            for(int ei=0;ei<4;ei++)
                #pragma unroll
                for(int j=0;j<20;j++) acc[ei][j]=0.f;
            for(int k=0;k<64;k++){
                float h0 = sH2[(4*eg+0)*65+k];
                float h1v= sH2[(4*eg+1)*65+k];
                float h2v= sH2[(4*eg+2)*65+k];
                float h3v= sH2[(4*eg+3)*65+k];
                #pragma unroll
                for(int j=0;j<20;j++){
                    float w = sW3[k*320+oo+16*j];
                    acc[0][j]+=h0*w; acc[1][j]+=h1v*w;
                    acc[2][j]+=h2v*w; acc[3][j]+=h3v*w;
                }
            }
            #pragma unroll
            for(int ei=0;ei<4;ei++){
                size_t base = (size_t)(ebase+4*eg+ei)*320;
                #pragma unroll
                for(int j=0;j<20;j++)
                    g_mix[base+oo+16*j] = acc[ei][j]*0.03125f; // (1/8)*(1/4)
            }
        }
        __syncthreads();
    }
}

// ---------------- K3: edge message + atomic scatter -------------------------
__global__ __launch_bounds__(256) void k_edge(
    const float* __restrict__ vecs,
    const int* __restrict__ send, const int* __restrict__ recv)
{
    __shared__ float smsg[8][704];
    int warp = threadIdx.x>>5, lane = threadIdx.x&31;
    int gw = blockIdx.x*8+warp, nw = gridDim.x*8;
    float* msg = smsg[warp];
    const float SQRT3 = 1.73205080757f;
    const float CRS   = 1.22474487139f;  // sqrt(3)/sqrt(2)
    for(int e=gw; e<Ne; e+=nw){
        float vx=vecs[3*e], vy=vecs[3*e+1], vz=vecs[3*e+2];
        float invr = rsqrtf(vx*vx+vy*vy+vz*vz);
        float ux=vx*invr, uy=vy*invr, uz=vz*invr;
        int s = send[e], r = recv[e];
        const float* su = g_s_up + s*64;
        const float* vu = g_v_up + s*192;
        const float* mx = g_mix + (size_t)e*320;
        #pragma unroll
        for(int t=0;t<2;t++){
            int c = lane + 32*t;
            float ms = su[c];
            float m0 = vu[3*c], m1 = vu[3*c+1], m2 = vu[3*c+2];
            float x0 = mx[c], x1 = mx[64+c], x2 = mx[128+c];
            float x3 = mx[192+c], x4 = mx[256+c];
            msg[c]    = ms*x0;
            msg[64+c] = (m0*ux+m1*uy+m2*uz)*x1;
            msg[128+0*192+c] = m0*x2;
            msg[128+1*192+c] = m1*x2;
            msg[128+2*192+c] = m2*x2;
            float s3 = ms*SQRT3*x3;
            msg[128+0*192+64+c] = s3*ux;
            msg[128+1*192+64+c] = s3*uy;
            msg[128+2*192+64+c] = s3*uz;
            float c4 = CRS*x4;
            msg[128+0*192+128+c] = (m1*uz-m2*uy)*c4;
            msg[128+1*192+128+c] = (m2*ux-m0*uz)*c4;
            msg[128+2*192+128+c] = (m0*uy-m1*ux)*c4;
        }
        __syncwarp();
        float* aggs = g_agg_s + (size_t)r*128;
        float* aggv = g_agg_v + (size_t)r*576;
        for(int g=lane; g<176; g+=32){
            const float4 v = *reinterpret_cast<const float4*>(&msg[4*g]);
            float* dst = (g<32) ? (aggs + 4*g) : (aggv + 4*g - 128);
            red4(dst, v.x, v.y, v.z, v.w);
        }
        __syncwarp();
    }
}

// ---------------- K4: down-projection + skip + gate -> output ---------------
// smem floats: Wds 16384 | Wdv 12288 | stage 8*704
#define OUT_SMEM_FLOATS (16384+12288+5632)
__global__ __launch_bounds__(256) void k_node_out(
    const float* __restrict__ Wds, const float* __restrict__ Wdv,
    float* __restrict__ out)
{
    extern __shared__ float sm[];
    float* sWds = sm;
    float* sWdv = sm+16384;
    float* sAgg = sm+16384+12288;
    int tid = threadIdx.x;
    for(int i=tid;i<16384;i+=256) sWds[i]=Wds[i];
    for(int i=tid;i<12288;i+=256) sWdv[i]=Wdv[i];
    __syncthreads();
    int warp = tid>>5, lane = tid&31;
    int gw = blockIdx.x*8+warp, nw = gridDim.x*8;
    const float ISNS = 0.08838834765f;  // 1/sqrt(128)
    const float ISNV = 0.07216878365f;  // 1/sqrt(192)
    float* st = sAgg + warp*704;
    for(int n=gw; n<Nn; n+=nw){
        for(int i=lane;i<128;i+=32) st[i]     = g_agg_s[n*128+i];
        for(int i=lane;i<576;i+=32) st[128+i] = g_agg_v[n*576+i];
        __syncwarp();
        float os[4]={0,0,0,0};
        for(int c=0;c<128;c++){
            float a = st[c];
            #pragma unroll
            for(int j=0;j<4;j++) os[j] += a*sWds[c*128+lane+32*j];
        }
        float ov[2][3]={{0,0,0},{0,0,0}};
        for(int c=0;c<192;c++){
            float a0 = st[128+c], a1 = st[128+192+c], a2 = st[128+384+c];
            #pragma unroll
            for(int j=0;j<2;j++){
                float w = sWdv[c*64+lane+32*j];
                ov[j][0]+=a0*w; ov[j][1]+=a1*w; ov[j][2]+=a2*w;
            }
        }
        #pragma unroll
        for(int j=0;j<4;j++) os[j] = os[j]*ISNS + g_skip_s[n*128+lane+32*j];
        #pragma unroll
        for(int j=0;j<2;j++)
            #pragma unroll
            for(int i=0;i<3;i++)
                ov[j][i] = ov[j][i]*ISNV + g_skip_v[n*192+3*(lane+32*j)+i];
        float g0 = sw(os[2]), g1 = sw(os[3]);
        float* o = out + (size_t)n*256;
        o[lane]    = sw(os[0]);
        o[lane+32] = sw(os[1]);
        #pragma unroll
        for(int i=0;i<3;i++){
            o[64+3*lane+i]      = ov[0][i]*g0;
            o[64+3*(lane+32)+i] = ov[1][i]*g1;
        }
        __syncwarp();
    }
}

// ---------------- launch ----------------------------------------------------
extern "C" void kernel_launch(void* const* d_in, const int* in_sizes, int n_in,
                              void* d_out, int out_size)
{
    const float* vectors  = (const float*)d_in[0];
    const float* node_s   = (const float*)d_in[1];
    const float* node_v   = (const float*)d_in[2];
    const int*   spec     = (const int*)  d_in[3];
    const int*   senders  = (const int*)  d_in[4];
    const int*   receivers= (const int*)  d_in[5];
    const float* Wss      = (const float*)d_in[6];
    const float* Wsv      = (const float*)d_in[7];
    const float* Wus      = (const float*)d_in[8];
    const float* Wuv      = (const float*)d_in[9];
    const float* W1       = (const float*)d_in[10];
    const float* W2       = (const float*)d_in[11];
    const float* W3       = (const float*)d_in[12];
    const float* Wds      = (const float*)d_in[13];
    const float* Wdv      = (const float*)d_in[14];
    float* out = (float*)d_out;

    void *pa, *pv;
    cudaGetSymbolAddress(&pa, g_agg_s);
    cudaGetSymbolAddress(&pv, g_agg_v);
    cudaMemsetAsync(pa, 0, (size_t)Nn*128*sizeof(float));
    cudaMemsetAsync(pv, 0, (size_t)Nn*576*sizeof(float));

    cudaFuncSetAttribute(k_mlp, cudaFuncAttributeMaxDynamicSharedMemorySize,
                         MLP_SMEM_FLOATS*4);
    cudaFuncSetAttribute(k_node_out, cudaFuncAttributeMaxDynamicSharedMemorySize,
                         OUT_SMEM_FLOATS*4);

    k_node_prep<<<1250, 256>>>(node_s, node_v, spec, Wss, Wsv, Wus, Wuv);
    k_mlp<<<148, 256, MLP_SMEM_FLOATS*4>>>(vectors, W1, W2, W3);
    k_edge<<<625, 256>>>(vectors, senders, receivers);
    k_node_out<<<148, 256, OUT_SMEM_FLOATS*4>>>(Wds, Wdv, out);
}